// round 1
// baseline (speedup 1.0000x reference)
#include <cuda_runtime.h>

#define IMG_W   512
#define IMG_HW  (512*512)
#define BLK9    9              // floats per 8-col block in smem (8 data + 1 pad)
#define ROWS    (64*BLK9)      // 576 floats per smem row
#define CHS     (8*ROWS)       // 4608 floats per channel
#define QOFF    (3*CHS)        // 13824 : QF[2][64] then QINV[2][64]
#define SMEM_FLOATS (QOFF + 256)
#define SMEM_BYTES  (SMEM_FLOATS*4)

__constant__ unsigned char c_lum[64] = {
 16,11,10,16,24,40,51,61, 12,12,14,19,26,58,60,55,
 14,13,16,24,40,57,69,56, 14,17,22,29,51,87,80,62,
 18,22,37,56,68,109,103,77, 24,35,55,64,81,104,113,92,
 49,64,78,87,103,121,120,101, 72,92,95,98,112,100,103,99};
__constant__ unsigned char c_chr[64] = {
 17,18,24,47,99,99,99,99, 18,21,26,66,99,99,99,99,
 24,26,56,99,99,99,99,99, 47,66,99,99,99,99,99,99,
 99,99,99,99,99,99,99,99, 99,99,99,99,99,99,99,99,
 99,99,99,99,99,99,99,99, 99,99,99,99,99,99,99,99};

// 0.5*cos(k*pi/16) coefficients
#define C1 0.4903926402016152f
#define C2 0.46193976625564337f
#define C3 0.4157348061512726f
#define C4 0.35355339059327373f
#define C5 0.27778511650980114f
#define C6 0.19134171618254492f
#define C7 0.09754516100806412f

__device__ __forceinline__ void dct8(const float* v, float* o) {
    float s0=v[0]+v[7], s1=v[1]+v[6], s2=v[2]+v[5], s3=v[3]+v[4];
    float d0=v[0]-v[7], d1=v[1]-v[6], d2=v[2]-v[5], d3=v[3]-v[4];
    float pa=s0+s3, pb=s1+s2, ma=s0-s3, mb=s1-s2;
    o[0] = C4*(pa+pb);
    o[4] = C4*(pa-pb);
    o[2] = fmaf(C2, ma,  C6*mb);
    o[6] = fmaf(C6, ma, -C2*mb);
    o[1] = fmaf(C1,d0, fmaf( C3,d1, fmaf( C5,d2,  C7*d3)));
    o[3] = fmaf(C3,d0, fmaf(-C7,d1, fmaf(-C1,d2, -C5*d3)));
    o[5] = fmaf(C5,d0, fmaf(-C1,d1, fmaf( C7,d2,  C3*d3)));
    o[7] = fmaf(C7,d0, fmaf(-C5,d1, fmaf( C3,d2, -C1*d3)));
}

__device__ __forceinline__ void idct8(const float* k, float* v) {
    float t0 = C4*(k[0]+k[4]);
    float t1 = C4*(k[0]-k[4]);
    float r0 = fmaf(C2,k[2],  C6*k[6]);
    float r1 = fmaf(C6,k[2], -C2*k[6]);
    float E0=t0+r0, E1=t1+r1, E2=t1-r1, E3=t0-r0;
    float O0 = fmaf(C1,k[1], fmaf( C3,k[3], fmaf( C5,k[5],  C7*k[7])));
    float O1 = fmaf(C3,k[1], fmaf(-C7,k[3], fmaf(-C1,k[5], -C5*k[7])));
    float O2 = fmaf(C5,k[1], fmaf(-C1,k[3], fmaf( C7,k[5],  C3*k[7])));
    float O3 = fmaf(C7,k[1], fmaf(-C5,k[3], fmaf( C3,k[5], -C1*k[7])));
    v[0]=E0+O0; v[7]=E0-O0;
    v[1]=E1+O1; v[6]=E1-O1;
    v[2]=E2+O2; v[5]=E2-O2;
    v[3]=E3+O3; v[4]=E3-O3;
}

// deq = (d + 0.5*tanh(15*d)) * q  with d = coef*qinv.   (round(d)==0 proven:
// QUALITY=50 -> q==base table; |coef| <= 0.5*(sum|D_row|)^2 <= 3.29, qmin=10
// -> |d| <= 0.33 < 0.5.)   FMA/ALU only: no MUFU (25M MUFU would cost ~190us).
__device__ __forceinline__ float soft_quant(float coef, float qi, float q) {
    float d = coef * qi;
    // E = exp(30*d) = 2^(d * 30*log2(e))
    float t  = d * 43.2808512266689f;
    float nf = t + 12582912.0f;                 // round-to-nearest int, magic
    float r  = t - (nf - 12582912.0f);          // r in [-0.5, 0.5]
    float p  = 1.3333558146e-3f;
    p = fmaf(p, r, 9.6181291076e-3f);
    p = fmaf(p, r, 5.5504108664e-2f);
    p = fmaf(p, r, 2.4022650696e-1f);
    p = fmaf(p, r, 6.9314718056e-1f);
    p = fmaf(p, r, 1.0f);
    int sc = (int)(((unsigned)__float_as_int(nf)) << 23);   // n << 23 exactly
    float E = __int_as_float(__float_as_int(p) + sc);
    // tanh = 1 - 2/(E+1); reciprocal via bit-trick + 3 Newton steps (FMA only)
    float den = E + 1.0f;
    float u = __int_as_float(0x7EF311C3 - __float_as_int(den));
    u = fmaf(fmaf(-den, u, 1.0f), u, u);
    u = fmaf(fmaf(-den, u, 1.0f), u, u);
    u = fmaf(fmaf(-den, u, 1.0f), u, u);
    float th = fmaf(-2.0f, u, 1.0f);
    float sr = fmaf(0.5f, th, d);
    return sr * q;
}

__global__ void __launch_bounds__(256)
jpeg_kernel(const float* __restrict__ in, float* __restrict__ out)
{
    extern __shared__ float sm[];
    const int tid  = threadIdx.x;
    const int base = blockIdx.y * (3*IMG_HW) + blockIdx.x * (8*IMG_W);

    // --- init quant tables in smem (q and 1/q) ---
    if (tid < 128) {
        int t = tid >> 6, j = tid & 63;
        float q = (float)(t ? c_chr[j] : c_lum[j]);
        sm[QOFF + t*64 + j]       = q;
        sm[QOFF + 128 + t*64 + j] = 1.0f / q;
    }
    __syncthreads();

    // --- P1: global load + forward color + column DCT -> smem ---
    #pragma unroll
    for (int it = 0; it < 2; ++it) {
        int col  = tid + it*256;
        int soff = (col >> 3)*BLK9 + (col & 7);
        float r[8], g[8], bl[8];
        #pragma unroll
        for (int x = 0; x < 8; x++) {
            int gi = base + x*IMG_W + col;
            r[x]  = in[gi];
            g[x]  = in[gi + IMG_HW];
            bl[x] = in[gi + 2*IMG_HW];
        }
        float a[8], o[8];
        #pragma unroll
        for (int x = 0; x < 8; x++)
            a[x] = fmaf(0.299f, r[x], fmaf(0.587f, g[x], 0.114f*bl[x])) - 0.5f;
        dct8(a, o);
        #pragma unroll
        for (int u = 0; u < 8; u++) sm[u*ROWS + soff] = o[u];

        #pragma unroll
        for (int x = 0; x < 8; x++)
            a[x] = fmaf(-0.168736f, r[x], fmaf(-0.331264f, g[x], 0.5f*bl[x]));
        dct8(a, o);
        #pragma unroll
        for (int u = 0; u < 8; u++) sm[CHS + u*ROWS + soff] = o[u];

        #pragma unroll
        for (int x = 0; x < 8; x++)
            a[x] = fmaf(0.5f, r[x], fmaf(-0.418688f, g[x], -0.081312f*bl[x]));
        dct8(a, o);
        #pragma unroll
        for (int u = 0; u < 8; u++) sm[2*CHS + u*ROWS + soff] = o[u];
    }
    __syncthreads();

    // --- P2: row DCT + quant/tanh/dequant, in place ---
    #pragma unroll
    for (int it = 0; it < 6; ++it) {
        int t   = tid + it*256;
        int c   = t >> 9;
        int rem = t & 511;
        int u   = rem >> 6;
        int blk = rem & 63;
        int off = c*CHS + u*ROWS + blk*BLK9;
        float v[8], k[8];
        #pragma unroll
        for (int y = 0; y < 8; y++) v[y] = sm[off + y];
        dct8(v, k);
        int qb = QOFF + ((c == 0) ? 0 : 64) + u*8;
        #pragma unroll
        for (int vv = 0; vv < 8; vv++) {
            float q  = sm[qb + vv];
            float qi = sm[qb + 128 + vv];
            sm[off + vv] = soft_quant(k[vv], qi, q);
        }
    }
    __syncthreads();

    // --- P3: column IDCT, in place ---
    #pragma unroll
    for (int it = 0; it < 6; ++it) {
        int t   = tid + it*256;
        int c   = t >> 9;
        int col = t & 511;
        int off = c*CHS + (col >> 3)*BLK9 + (col & 7);
        float k[8], z[8];
        #pragma unroll
        for (int u = 0; u < 8; u++) k[u] = sm[off + u*ROWS];
        idct8(k, z);
        #pragma unroll
        for (int x = 0; x < 8; x++) sm[off + x*ROWS] = z[x];
    }
    __syncthreads();

    // --- P4: row IDCT + inverse color + clip + coalesced float4 stores ---
    #pragma unroll
    for (int it = 0; it < 2; ++it) {
        int t   = tid + it*256;
        int x   = t >> 6;
        int blk = t & 63;
        int off = x*ROWS + blk*BLK9;
        float z[8], rec0[8], rec1[8], rec2[8];
        #pragma unroll
        for (int v = 0; v < 8; v++) z[v] = sm[off + v];
        idct8(z, rec0);
        #pragma unroll
        for (int v = 0; v < 8; v++) z[v] = sm[CHS + off + v];
        idct8(z, rec1);
        #pragma unroll
        for (int v = 0; v < 8; v++) z[v] = sm[2*CHS + off + v];
        idct8(z, rec2);

        float R[8], G[8], B[8];
        #pragma unroll
        for (int y = 0; y < 8; y++) {
            float Y  = rec0[y] + 0.5f;
            float cb = rec1[y];
            float cr = rec2[y];
            R[y] = __saturatef(fmaf(1.402f, cr, Y));
            G[y] = __saturatef(fmaf(-0.344136f, cb, fmaf(-0.714136f, cr, Y)));
            B[y] = __saturatef(fmaf(1.772f, cb, Y));
        }
        int go = base + x*IMG_W + blk*8;
        float4* p0 = (float4*)(out + go);
        float4* p1 = (float4*)(out + go + IMG_HW);
        float4* p2 = (float4*)(out + go + 2*IMG_HW);
        p0[0] = make_float4(R[0],R[1],R[2],R[3]);
        p0[1] = make_float4(R[4],R[5],R[6],R[7]);
        p1[0] = make_float4(G[0],G[1],G[2],G[3]);
        p1[1] = make_float4(G[4],G[5],G[6],G[7]);
        p2[0] = make_float4(B[0],B[1],B[2],B[3]);
        p2[1] = make_float4(B[4],B[5],B[6],B[7]);
    }
}

extern "C" void kernel_launch(void* const* d_in, const int* in_sizes, int n_in,
                              void* d_out, int out_size)
{
    const float* in = (const float*)d_in[0];
    float* out = (float*)d_out;
    cudaFuncSetAttribute(jpeg_kernel,
                         cudaFuncAttributeMaxDynamicSharedMemorySize, SMEM_BYTES);
    dim3 grid(64, 32);   // 64 strips of 8 rows per image, 32 images
    jpeg_kernel<<<grid, 256, SMEM_BYTES>>>(in, out);
}

// round 3
// speedup vs baseline: 1.3846x; 1.3846x over previous
#include <cuda_runtime.h>

#define IMG_W   512
#define IMG_HW  (512*512)
#define BLK9    9                 // floats per 8-col block (8 data + 1 pad)
#define NBLK    16                // blocks per 128-wide strip
#define RW      (NBLK*BLK9)       // 144 floats per row per channel
#define CHS     (8*RW)            // 1152 floats per channel
#define QOFF    (3*CHS)           // 3456
#define SMEM_FLOATS (QOFF + 256)  // + float2 qtab[128]

__constant__ unsigned char c_lum[64] = {
 16,11,10,16,24,40,51,61, 12,12,14,19,26,58,60,55,
 14,13,16,24,40,57,69,56, 14,17,22,29,51,87,80,62,
 18,22,37,56,68,109,103,77, 24,35,55,64,81,104,113,92,
 49,64,78,87,103,121,120,101, 72,92,95,98,112,100,103,99};
__constant__ unsigned char c_chr[64] = {
 17,18,24,47,99,99,99,99, 18,21,26,66,99,99,99,99,
 24,26,56,99,99,99,99,99, 47,66,99,99,99,99,99,99,
 99,99,99,99,99,99,99,99, 99,99,99,99,99,99,99,99,
 99,99,99,99,99,99,99,99, 99,99,99,99,99,99,99,99};

// 0.5*cos(k*pi/16)
#define C1 0.4903926402016152f
#define C2 0.46193976625564337f
#define C3 0.4157348061512726f
#define C4 0.35355339059327373f
#define C5 0.27778511650980114f
#define C6 0.19134171618254492f
#define C7 0.09754516100806412f

__device__ __forceinline__ void dct8(const float* v, float* o) {
    float s0=v[0]+v[7], s1=v[1]+v[6], s2=v[2]+v[5], s3=v[3]+v[4];
    float d0=v[0]-v[7], d1=v[1]-v[6], d2=v[2]-v[5], d3=v[3]-v[4];
    float pa=s0+s3, pb=s1+s2, ma=s0-s3, mb=s1-s2;
    o[0] = C4*(pa+pb);
    o[4] = C4*(pa-pb);
    o[2] = fmaf(C2, ma,  C6*mb);
    o[6] = fmaf(C6, ma, -C2*mb);
    o[1] = fmaf(C1,d0, fmaf( C3,d1, fmaf( C5,d2,  C7*d3)));
    o[3] = fmaf(C3,d0, fmaf(-C7,d1, fmaf(-C1,d2, -C5*d3)));
    o[5] = fmaf(C5,d0, fmaf(-C1,d1, fmaf( C7,d2,  C3*d3)));
    o[7] = fmaf(C7,d0, fmaf(-C5,d1, fmaf( C3,d2, -C1*d3)));
}

__device__ __forceinline__ void idct8(const float* k, float* v) {
    float t0 = C4*(k[0]+k[4]);
    float t1 = C4*(k[0]-k[4]);
    float r0 = fmaf(C2,k[2],  C6*k[6]);
    float r1 = fmaf(C6,k[2], -C2*k[6]);
    float E0=t0+r0, E1=t1+r1, E2=t1-r1, E3=t0-r0;
    float O0 = fmaf(C1,k[1], fmaf( C3,k[3], fmaf( C5,k[5],  C7*k[7])));
    float O1 = fmaf(C3,k[1], fmaf(-C7,k[3], fmaf(-C1,k[5], -C5*k[7])));
    float O2 = fmaf(C5,k[1], fmaf(-C1,k[3], fmaf( C7,k[5],  C3*k[7])));
    float O3 = fmaf(C7,k[1], fmaf(-C5,k[3], fmaf( C3,k[5], -C1*k[7])));
    v[0]=E0+O0; v[7]=E0-O0;
    v[1]=E1+O1; v[6]=E1-O1;
    v[2]=E2+O2; v[5]=E2-O2;
    v[3]=E3+O3; v[4]=E3-O3;
}

// deq = (d + 0.5*tanh(15*d)) * q,  d = coef*qinv.  round(d)==0 proven:
// |coef| <= 0.5*2.828^2 = 4.0, q_min = 10 -> |d| <= 0.40 < 0.5.
// tanh(15d) = 1 - 2/(e^{30d}+1);  0.5*tanh = 0.5 - 1/(E+1).
// MUFU (ex2 + rcp) keeps this off the FMA pipe: 2 MUFU + ~5 fma-pipe ops.
__device__ __forceinline__ float soft_quant(float coef, float qi, float q) {
    float d = coef * qi;
    float t = d * 43.2808512266689f;          // 30*log2(e)
    float E;  asm("ex2.approx.f32 %0, %1;" : "=f"(E) : "f"(t));
    float den = E + 1.0f;
    float r;  asm("rcp.approx.f32 %0, %1;" : "=f"(r) : "f"(den));
    float sr = (d + 0.5f) - r;
    return sr * q;
}

__global__ void __launch_bounds__(128, 8)
jpeg_kernel(const float* __restrict__ in, float* __restrict__ out)
{
    __shared__ float sm[SMEM_FLOATS];
    float2* qt = (float2*)(sm + QOFF);

    const int tid = threadIdx.x;
    const int sx  = blockIdx.x & 3;          // which 128-col strip
    const int sy  = blockIdx.x >> 2;         // which 8-row strip
    const int base = blockIdx.y * (3*IMG_HW) + sy * (8*IMG_W) + sx * 128;

    // quant tables: float2{q, 1/q}[2][64]  (covered by the P1 barrier)
    {
        int c = tid >> 6, j = tid & 63;
        float q = (float)(c ? c_chr[j] : c_lum[j]);
        qt[tid] = make_float2(q, 1.0f / q);
    }

    // ---- P1: load + forward color + row-DCT (along y) -> smem ----
    {
        const int x   = tid >> 4;
        const int blk = tid & 15;
        const int gi  = base + x*IMG_W + blk*8;
        const float4* p0 = (const float4*)(in + gi);
        const float4* p1 = (const float4*)(in + gi + IMG_HW);
        const float4* p2 = (const float4*)(in + gi + 2*IMG_HW);
        float4 ra = p0[0], rb = p0[1];
        float4 ga = p1[0], gb = p1[1];
        float4 ba = p2[0], bb = p2[1];
        float r[8]  = {ra.x,ra.y,ra.z,ra.w, rb.x,rb.y,rb.z,rb.w};
        float g[8]  = {ga.x,ga.y,ga.z,ga.w, gb.x,gb.y,gb.z,gb.w};
        float bl[8] = {ba.x,ba.y,ba.z,ba.w, bb.x,bb.y,bb.z,bb.w};

        const int soff = x*RW + blk*BLK9;
        float a[8], o[8];
        #pragma unroll
        for (int y = 0; y < 8; y++)
            a[y] = fmaf(0.299f, r[y], fmaf(0.587f, g[y], 0.114f*bl[y])) - 0.5f;
        dct8(a, o);
        #pragma unroll
        for (int v = 0; v < 8; v++) sm[soff + v] = o[v];

        #pragma unroll
        for (int y = 0; y < 8; y++)
            a[y] = fmaf(-0.168736f, r[y], fmaf(-0.331264f, g[y], 0.5f*bl[y]));
        dct8(a, o);
        #pragma unroll
        for (int v = 0; v < 8; v++) sm[CHS + soff + v] = o[v];

        #pragma unroll
        for (int y = 0; y < 8; y++)
            a[y] = fmaf(0.5f, r[y], fmaf(-0.418688f, g[y], -0.081312f*bl[y]));
        dct8(a, o);
        #pragma unroll
        for (int v = 0; v < 8; v++) sm[2*CHS + soff + v] = o[v];
    }
    __syncthreads();

    // ---- P2: column-DCT (along x) + quant/tanh/dequant + column-IDCT, in place ----
    {
        const int v   = tid & 7;
        const int blk = tid >> 3;            // 0..15
        // preload quant pairs for this v (independent of the DCT chain)
        float2 qq[8];
        const int qb0 = tid & 7;
        #pragma unroll
        for (int u = 0; u < 8; u++) qq[u] = qt[qb0 + u*8];
        float2 qqc[8];
        #pragma unroll
        for (int u = 0; u < 8; u++) qqc[u] = qt[64 + qb0 + u*8];

        #pragma unroll
        for (int c = 0; c < 3; c++) {
            const int coff = c*CHS + blk*BLK9 + v;
            float k[8], K[8], z[8];
            #pragma unroll
            for (int x = 0; x < 8; x++) k[x] = sm[coff + x*RW];
            dct8(k, K);
            #pragma unroll
            for (int u = 0; u < 8; u++) {
                float2 p = (c == 0) ? qq[u] : qqc[u];
                K[u] = soft_quant(K[u], p.y, p.x);
            }
            idct8(K, z);
            #pragma unroll
            for (int x = 0; x < 8; x++) sm[coff + x*RW] = z[x];
        }
    }
    __syncthreads();

    // ---- P3: row-IDCT (along v) + inverse color + clip + stores ----
    {
        const int x   = tid >> 4;
        const int blk = tid & 15;
        const int soff = x*RW + blk*BLK9;
        float z[8], rec0[8], rec1[8], rec2[8];
        #pragma unroll
        for (int v = 0; v < 8; v++) z[v] = sm[soff + v];
        idct8(z, rec0);
        #pragma unroll
        for (int v = 0; v < 8; v++) z[v] = sm[CHS + soff + v];
        idct8(z, rec1);
        #pragma unroll
        for (int v = 0; v < 8; v++) z[v] = sm[2*CHS + soff + v];
        idct8(z, rec2);

        float R[8], G[8], B[8];
        #pragma unroll
        for (int y = 0; y < 8; y++) {
            float Y  = rec0[y] + 0.5f;
            float cb = rec1[y];
            float cr = rec2[y];
            R[y] = __saturatef(fmaf(1.402f, cr, Y));
            G[y] = __saturatef(fmaf(-0.344136f, cb, fmaf(-0.714136f, cr, Y)));
            B[y] = __saturatef(fmaf(1.772f, cb, Y));
        }
        const int go = base + x*IMG_W + blk*8;
        float4* p0 = (float4*)(out + go);
        float4* p1 = (float4*)(out + go + IMG_HW);
        float4* p2 = (float4*)(out + go + 2*IMG_HW);
        p0[0] = make_float4(R[0],R[1],R[2],R[3]);
        p0[1] = make_float4(R[4],R[5],R[6],R[7]);
        p1[0] = make_float4(G[0],G[1],G[2],G[3]);
        p1[1] = make_float4(G[4],G[5],G[6],G[7]);
        p2[0] = make_float4(B[0],B[1],B[2],B[3]);
        p2[1] = make_float4(B[4],B[5],B[6],B[7]);
    }
}

extern "C" void kernel_launch(void* const* d_in, const int* in_sizes, int n_in,
                              void* d_out, int out_size)
{
    const float* in = (const float*)d_in[0];
    float* out = (float*)d_out;
    dim3 grid(256, 32);   // 4 col-strips x 64 row-strips, 32 images
    jpeg_kernel<<<grid, 128>>>(in, out);
}